// round 13
// baseline (speedup 1.0000x reference)
#include <cuda_runtime.h>
#include <cuda_bf16.h>
#include <math.h>

// ---------------------------------------------------------------------------
// mean over all (i,j) of: same(i,j) ? max(1-cos,0) : cos, with cos = pairwise
// cosine of row-normalized inputs.
//
// Algebraic collapse (clamp provably inactive; rel_err==0.0 confirmed):
//   sum = S1.S2 + sum_c [ cnt1_c*cnt2_c - 2 * T1_c . T2_c ]
// T_c = class-sum of normalized rows.  O(N*D).
//
// R12: R11 falsified the MLP theory for the reduce (single load wave still
// 14.7us). Every slow variant shared RED -> __threadfence -> election; the
// only fast kernel (K2) has none. This version removes ALL global atomics,
// fences and elections: 3 kernels ordered by launch boundaries.
//   K2: partials, TRANSPOSED layout g_partT[c][q][bid] (contiguous slices)
//   K3: warp per (c,q): 4 coalesced LDG.128/lane + shuffle reduce + STG
//   K4: 1 block: counts + fp64 finalize
// No persistent mutable state (dense overwrite or never-written==0).
// ---------------------------------------------------------------------------

#define NCLASS   16
#define NCEFF    32           // 16 classes x 2 tensors
#define DIM      256
#define DIMQ     (DIM / 4)    // 64 dim-quads
#define ROWS_PB  64
#define MAXBLK   128          // (4096+4096)/64
#define NTHREADS 256
#define ROWS_PW  8            // rows per warp in K2 norm pass

struct __align__(16) Entry {
    const float* ptr;
    float        inv;
    int          cls;
};

__device__ float4 g_partT[NCEFF][DIMQ][MAXBLK];   // 4 MB; [c][q][bid] contiguous in bid
__device__ int    g_cntp[MAXBLK][NCEFF];          // dense overwrite (or stays 0)
__device__ float4 g_T4[NCEFF * DIMQ];             // 32 KB; K3 fully overwrites

// ======================= K2: per-block partial tiles ========================
__global__ void __launch_bounds__(NTHREADS, 1)
ci_partial_kernel(const float* __restrict__ x1,
                  const int* __restrict__ lab1, int n1,
                  const float* __restrict__ x2,
                  const int* __restrict__ lab2, int n2) {
    __shared__ Entry         sSorted[ROWS_PB];
    __shared__ const float*  sPtr[ROWS_PB];
    __shared__ int           sCls[ROWS_PB];
    __shared__ int           sPos[ROWS_PB];
    __shared__ int           sCnt[NCEFF];
    __shared__ int           sOff[NCEFF];

    const int tid  = threadIdx.x;
    const int lane = tid & 31;
    const int wid  = tid >> 5;
    const int bid  = blockIdx.x;

    if (tid < NCEFF) sCnt[tid] = 0;
    __syncthreads();

    const int ntot  = n1 + n2;
    const int base  = bid * ROWS_PB;
    const int chunk = min(ROWS_PB, ntot - base);

    // ---- prologue: labels, pointers, counts, ranks ------------------------
    if (tid < chunk) {
        int row = base + tid;
        const float* xp;
        int c;
        if (row < n1) { xp = x1 + (size_t)row * DIM;        c = lab1[row] & (NCLASS - 1); }
        else          { xp = x2 + (size_t)(row - n1) * DIM; c = (lab2[row - n1] & (NCLASS - 1)) + NCLASS; }
        sPtr[tid] = xp;
        sCls[tid] = c;
        sPos[tid] = atomicAdd(&sCnt[c], 1);     // smem only, 64 ops
    }
    __syncthreads();

    // ---- warp 0: exclusive prefix scan of counts -> bucket offsets --------
    if (wid == 0) {
        int v = sCnt[lane];
        int s = v;
        #pragma unroll
        for (int o = 1; o < 32; o <<= 1) {
            int u = __shfl_up_sync(0xFFFFFFFFu, s, o);
            if (lane >= o) s += u;
        }
        sOff[lane] = s - v;   // exclusive
    }
    __syncthreads();

    // ---- norm pass: warp handles 8 rows, ALL 16 LDG.128 front-batched -----
    {
        const int i0 = wid * ROWS_PW;
        const float4* ps[ROWS_PW];
        #pragma unroll
        for (int j = 0; j < ROWS_PW; j++)
            ps[j] = reinterpret_cast<const float4*>(
                (i0 + j < chunk) ? sPtr[i0 + j] : x1);

        float4 A[ROWS_PW], B[ROWS_PW];
        #pragma unroll
        for (int j = 0; j < ROWS_PW; j++) {
            A[j] = ps[j][lane * 2];
            B[j] = ps[j][lane * 2 + 1];
        }
        float ss[ROWS_PW];
        #pragma unroll
        for (int j = 0; j < ROWS_PW; j++)
            ss[j] = A[j].x * A[j].x + A[j].y * A[j].y + A[j].z * A[j].z + A[j].w * A[j].w
                  + B[j].x * B[j].x + B[j].y * B[j].y + B[j].z * B[j].z + B[j].w * B[j].w;
        #pragma unroll
        for (int o = 16; o > 0; o >>= 1) {
            #pragma unroll
            for (int j = 0; j < ROWS_PW; j++)
                ss[j] += __shfl_xor_sync(0xFFFFFFFFu, ss[j], o);
        }
        if (lane == 0) {
            #pragma unroll
            for (int j = 0; j < ROWS_PW; j++) {
                int i = i0 + j;
                if (i < chunk) {
                    int c   = sCls[i];
                    int idx = sOff[c] + sPos[i];
                    sSorted[idx].ptr = (const float*)ps[j];
                    sSorted[idx].inv = 1.0f / fmaxf(sqrtf(ss[j]), 1e-8f);
                    sSorted[idx].cls = c;
                }
            }
        }
    }
    __syncthreads();

    // ---- phase B: scan sorted runs; transposed STG partial -----------------
    {
        const int gq = tid >> 6;          // 0..3
        const int q  = tid & (DIMQ - 1);  // 0..63
        #pragma unroll
        for (int ci = 0; ci < 8; ci++) {
            int c = gq * 8 + ci;
            int s = sOff[c];
            int e = s + sCnt[c];
            float4 acc = make_float4(0.f, 0.f, 0.f, 0.f);
            for (int k = s; k < e; k++) {
                Entry en = sSorted[k];                                  // bcast LDS.128
                float4 v = reinterpret_cast<const float4*>(en.ptr)[q];  // L1 hit
                acc.x += v.x * en.inv;
                acc.y += v.y * en.inv;
                acc.z += v.z * en.inv;
                acc.w += v.w * en.inv;
            }
            g_partT[c][q][bid] = acc;   // plain STG.128, transposed layout
        }
    }
    if (tid < NCEFF) g_cntp[bid][tid] = sCnt[tid];
}

// ======================= K3: warp-per-(c,q) coalesced reduce ================
// 256 blocks x 8 warps = 2048 warps = NCEFF*DIMQ tasks.
// Each (c,q): 128 contiguous float4 (2KB). Lane reads 4 coalesced float4s.
__global__ void __launch_bounds__(NTHREADS, 1)
ci_reduce_kernel() {
    const int tid  = threadIdx.x;
    const int lane = tid & 31;
    const int w    = tid >> 5;
    const int c    = blockIdx.x >> 3;
    const int q    = (blockIdx.x & 7) * 8 + w;

    const float4* p = &g_partT[c][q][0];
    float4 a = p[lane];
    float4 b = p[lane + 32];
    float4 d = p[lane + 64];
    float4 e = p[lane + 96];
    a.x = (a.x + b.x) + (d.x + e.x);
    a.y = (a.y + b.y) + (d.y + e.y);
    a.z = (a.z + b.z) + (d.z + e.z);
    a.w = (a.w + b.w) + (d.w + e.w);
    #pragma unroll
    for (int o = 16; o > 0; o >>= 1) {
        a.x += __shfl_xor_sync(0xFFFFFFFFu, a.x, o);
        a.y += __shfl_xor_sync(0xFFFFFFFFu, a.y, o);
        a.z += __shfl_xor_sync(0xFFFFFFFFu, a.z, o);
        a.w += __shfl_xor_sync(0xFFFFFFFFu, a.w, o);
    }
    if (lane == 0)
        g_T4[c * DIMQ + q] = a;    // plain STG.128
}

// ======================= K4: single-block finalize ==========================
__global__ void __launch_bounds__(NTHREADS, 1)
ci_final_kernel(float* __restrict__ out, int n1, int n2) {
    __shared__ int    sCntPart[NCEFF][8];
    __shared__ int    sCnt[NCEFF];
    __shared__ double sRed[NTHREADS / 32];

    const int tid  = threadIdx.x;
    const int lane = tid & 31;

    // ---- counts: 32 classes x 8 parts; each part sums 16 g_cntp rows -------
    {
        const int c    = tid & (NCEFF - 1);
        const int part = tid >> 5;   // 0..7
        int s = 0;
        #pragma unroll
        for (int k = 0; k < MAXBLK / 8; k++)
            s += g_cntp[part * (MAXBLK / 8) + k][c];
        sCntPart[c][part] = s;
    }
    __syncthreads();
    if (tid < NCEFF) {
        int t = 0;
        #pragma unroll
        for (int p = 0; p < 8; p++) t += sCntPart[tid][p];
        sCnt[tid] = t;
    }
    __syncthreads();

    // ---- fp64 finalize -------------------------------------------------------
    const float* gT = (const float*)g_T4;          // [NCEFF*DIM]
    const int d = tid;  // 0..255 == DIM
    double s1 = 0.0, s2 = 0.0, t = 0.0;
    #pragma unroll
    for (int cc = 0; cc < NCLASS; cc++) {
        double av = (double)gT[cc * DIM + d];
        double bv = (double)gT[(cc + NCLASS) * DIM + d];
        s1 += av;
        s2 += bv;
        t  += av * bv;
    }
    double part = s1 * s2 - 2.0 * t;
    #pragma unroll
    for (int o = 16; o > 0; o >>= 1)
        part += __shfl_xor_sync(0xFFFFFFFFu, part, o);
    if (lane == 0) sRed[tid >> 5] = part;
    __syncthreads();
    if (tid == 0) {
        double tot = 0.0;
        #pragma unroll
        for (int w = 0; w < NTHREADS / 32; w++) tot += sRed[w];
        double cc = 0.0;
        #pragma unroll
        for (int k = 0; k < NCLASS; k++)
            cc += (double)sCnt[k] * (double)sCnt[k + NCLASS];
        out[0] = (float)((tot + cc) / ((double)n1 * (double)n2));
    }
}

extern "C" void kernel_launch(void* const* d_in, const int* in_sizes, int n_in,
                              void* d_out, int out_size) {
    const float* mmd1 = (const float*)d_in[0];
    const float* mmd2 = (const float*)d_in[1];
    const int*   lab1 = (const int*)d_in[2];
    const int*   lab2 = (const int*)d_in[3];

    int n1 = in_sizes[0] / DIM;
    int n2 = in_sizes[1] / DIM;
    int ntot = n1 + n2;
    int nblk = (ntot + ROWS_PB - 1) / ROWS_PB;
    if (nblk > MAXBLK) nblk = MAXBLK;   // fixed shapes: 128 exactly
    // (slices never written stay zero from module load -> sums stay correct)

    ci_partial_kernel<<<nblk, NTHREADS>>>(mmd1, lab1, n1, mmd2, lab2, n2);
    ci_reduce_kernel<<<NCEFF * 8, NTHREADS>>>();
    ci_final_kernel<<<1, NTHREADS>>>((float*)d_out, n1, n2);
}

// round 14
// speedup vs baseline: 1.1895x; 1.1895x over previous
#include <cuda_runtime.h>
#include <cuda_bf16.h>
#include <math.h>

// ---------------------------------------------------------------------------
// mean over all (i,j) of: same(i,j) ? max(1-cos,0) : cos, with cos = pairwise
// cosine of row-normalized inputs.
//
// Algebraic collapse (clamp provably inactive; rel_err==0.0 confirmed):
//   sum = S1.S2 + sum_c [ cnt1_c*cnt2_c - 2 * T1_c . T2_c ]
// T_c = class-sum of normalized rows.  O(N*D).
//
// R13 cost model (from R12 decomposition):
//   - dense coalesced K2 = ~3us (transposed scatter was +7us -> reverted)
//   - every tiny kernel pays a ~4us launch floor -> merge reduce+finalize
//   - elections cost ~linear in block count -> keep coupling at 16 blocks
// K2: dense per-block partial tiles (proven).
// K3: 16 blocks; block b owns dims [16b,16b+16): reads its 256KB column of
//     g_part from L2 (64 batched loads/thread), fp64-reduces to ONE scalar,
//     atomicAdd(double) + 16-block election; last block writes out + resets.
// ---------------------------------------------------------------------------

#define NCLASS   16
#define NCEFF    32           // 16 classes x 2 tensors
#define DIM      256
#define DIMQ     (DIM / 4)    // 64 dim-quads
#define ROWS_PB  64
#define MAXBLK   128          // (4096+4096)/64
#define NTHREADS 256
#define ROWS_PW  8            // rows per warp in K2 norm pass
#define QPB      4            // quads per K3 block
#define K3BLKS   (DIMQ / QPB) // 16

struct __align__(16) Entry {
    const float* ptr;
    float        inv;
    int          cls;
};

__device__ float4       g_part[MAXBLK][NCEFF][DIMQ];  // 4 MB, dense overwrite
__device__ int          g_cntp[MAXBLK][NCEFF];        // dense overwrite
__device__ double       g_sum;                        // atomic accum; last block resets
__device__ unsigned int g_done;

// ======================= K2: per-block partial tiles ========================
__global__ void __launch_bounds__(NTHREADS, 1)
ci_partial_kernel(const float* __restrict__ x1,
                  const int* __restrict__ lab1, int n1,
                  const float* __restrict__ x2,
                  const int* __restrict__ lab2, int n2) {
    __shared__ Entry         sSorted[ROWS_PB];
    __shared__ const float*  sPtr[ROWS_PB];
    __shared__ int           sCls[ROWS_PB];
    __shared__ int           sPos[ROWS_PB];
    __shared__ int           sCnt[NCEFF];
    __shared__ int           sOff[NCEFF];

    const int tid  = threadIdx.x;
    const int lane = tid & 31;
    const int wid  = tid >> 5;
    const int bid  = blockIdx.x;

    if (tid < NCEFF) sCnt[tid] = 0;
    __syncthreads();

    const int ntot  = n1 + n2;
    const int base  = bid * ROWS_PB;
    const int chunk = min(ROWS_PB, ntot - base);

    // ---- prologue: labels, pointers, counts, ranks ------------------------
    if (tid < chunk) {
        int row = base + tid;
        const float* xp;
        int c;
        if (row < n1) { xp = x1 + (size_t)row * DIM;        c = lab1[row] & (NCLASS - 1); }
        else          { xp = x2 + (size_t)(row - n1) * DIM; c = (lab2[row - n1] & (NCLASS - 1)) + NCLASS; }
        sPtr[tid] = xp;
        sCls[tid] = c;
        sPos[tid] = atomicAdd(&sCnt[c], 1);     // smem only, 64 ops
    }
    __syncthreads();

    // ---- warp 0: exclusive prefix scan of counts -> bucket offsets --------
    if (wid == 0) {
        int v = sCnt[lane];
        int s = v;
        #pragma unroll
        for (int o = 1; o < 32; o <<= 1) {
            int u = __shfl_up_sync(0xFFFFFFFFu, s, o);
            if (lane >= o) s += u;
        }
        sOff[lane] = s - v;   // exclusive
    }
    __syncthreads();

    // ---- norm pass: warp handles 8 rows, ALL 16 LDG.128 front-batched -----
    {
        const int i0 = wid * ROWS_PW;
        const float4* ps[ROWS_PW];
        #pragma unroll
        for (int j = 0; j < ROWS_PW; j++)
            ps[j] = reinterpret_cast<const float4*>(
                (i0 + j < chunk) ? sPtr[i0 + j] : x1);

        float4 A[ROWS_PW], B[ROWS_PW];
        #pragma unroll
        for (int j = 0; j < ROWS_PW; j++) {
            A[j] = ps[j][lane * 2];
            B[j] = ps[j][lane * 2 + 1];
        }
        float ss[ROWS_PW];
        #pragma unroll
        for (int j = 0; j < ROWS_PW; j++)
            ss[j] = A[j].x * A[j].x + A[j].y * A[j].y + A[j].z * A[j].z + A[j].w * A[j].w
                  + B[j].x * B[j].x + B[j].y * B[j].y + B[j].z * B[j].z + B[j].w * B[j].w;
        #pragma unroll
        for (int o = 16; o > 0; o >>= 1) {
            #pragma unroll
            for (int j = 0; j < ROWS_PW; j++)
                ss[j] += __shfl_xor_sync(0xFFFFFFFFu, ss[j], o);
        }
        if (lane == 0) {
            #pragma unroll
            for (int j = 0; j < ROWS_PW; j++) {
                int i = i0 + j;
                if (i < chunk) {
                    int c   = sCls[i];
                    int idx = sOff[c] + sPos[i];
                    sSorted[idx].ptr = (const float*)ps[j];
                    sSorted[idx].inv = 1.0f / fmaxf(sqrtf(ss[j]), 1e-8f);
                    sSorted[idx].cls = c;
                }
            }
        }
    }
    __syncthreads();

    // ---- phase B: scan sorted runs; DENSE coalesced STG partial tile -------
    {
        const int gq = tid >> 6;          // 0..3
        const int q  = tid & (DIMQ - 1);  // 0..63
        #pragma unroll
        for (int ci = 0; ci < 8; ci++) {
            int c = gq * 8 + ci;
            int s = sOff[c];
            int e = s + sCnt[c];
            float4 acc = make_float4(0.f, 0.f, 0.f, 0.f);
            for (int k = s; k < e; k++) {
                Entry en = sSorted[k];                                  // bcast LDS.128
                float4 v = reinterpret_cast<const float4*>(en.ptr)[q];  // L1 hit
                acc.x += v.x * en.inv;
                acc.y += v.y * en.inv;
                acc.z += v.z * en.inv;
                acc.w += v.w * en.inv;
            }
            g_part[bid][c][q] = acc;   // coalesced STG.128
        }
    }
    if (tid < NCEFF) g_cntp[bid][tid] = sCnt[tid];
}

// ================= K3: column reduce + fp64 finalize (16 blocks) ============
// block b owns quads [4b, 4b+4) = dims [16b, 16b+16).
// 256 threads: c = tid>>3 (32), half = (tid>>2)&1 (64 bids each), ql = tid&3.
__global__ void __launch_bounds__(NTHREADS, 1)
ci_reduce_final_kernel(float* __restrict__ out, int n1, int n2) {
    __shared__ float4       sHalf[2][NCEFF][QPB];
    __shared__ float        sTf[NCEFF][QPB][4];   // [class][quad][comp]
    __shared__ int          sCntPart[NCEFF][8];
    __shared__ int          sCnt[NCEFF];
    __shared__ double       sCntTerm;
    __shared__ unsigned int sIsLast;

    const int tid  = threadIdx.x;
    const int ql   = tid & 3;
    const int half = (tid >> 2) & 1;
    const int c    = tid >> 3;
    const int q    = blockIdx.x * QPB + ql;

    // ---- 64 loads/thread over bids, batched 8-wide (L2-resident) ----------
    {
        const float4* base = &g_part[half * 64][c][q];
        const size_t  str  = (size_t)NCEFF * DIMQ;   // float4s between slices
        float4 a0 = make_float4(0.f, 0.f, 0.f, 0.f);
        float4 a1 = make_float4(0.f, 0.f, 0.f, 0.f);
        for (int k = 0; k < 64; k += 8) {
            float4 v0 = base[(k + 0) * str];
            float4 v1 = base[(k + 1) * str];
            float4 v2 = base[(k + 2) * str];
            float4 v3 = base[(k + 3) * str];
            float4 v4 = base[(k + 4) * str];
            float4 v5 = base[(k + 5) * str];
            float4 v6 = base[(k + 6) * str];
            float4 v7 = base[(k + 7) * str];
            a0.x += (v0.x + v1.x) + (v2.x + v3.x);
            a0.y += (v0.y + v1.y) + (v2.y + v3.y);
            a0.z += (v0.z + v1.z) + (v2.z + v3.z);
            a0.w += (v0.w + v1.w) + (v2.w + v3.w);
            a1.x += (v4.x + v5.x) + (v6.x + v7.x);
            a1.y += (v4.y + v5.y) + (v6.y + v7.y);
            a1.z += (v4.z + v5.z) + (v6.z + v7.z);
            a1.w += (v4.w + v5.w) + (v6.w + v7.w);
        }
        a0.x += a1.x; a0.y += a1.y; a0.z += a1.z; a0.w += a1.w;
        sHalf[half][c][ql] = a0;
    }

    // ---- block 0 stages class counts in parallel ---------------------------
    if (blockIdx.x == 0) {
        const int cc   = tid & (NCEFF - 1);
        const int part = tid >> 5;   // 0..7, 16 bids each
        int s = 0;
        #pragma unroll
        for (int k = 0; k < MAXBLK / 8; k++)
            s += g_cntp[part * (MAXBLK / 8) + k][cc];
        sCntPart[cc][part] = s;
    }
    __syncthreads();

    // ---- combine halves ------------------------------------------------------
    if (half == 0) {
        float4 t0 = sHalf[0][c][ql];
        float4 t1 = sHalf[1][c][ql];
        sTf[c][ql][0] = t0.x + t1.x;
        sTf[c][ql][1] = t0.y + t1.y;
        sTf[c][ql][2] = t0.z + t1.z;
        sTf[c][ql][3] = t0.w + t1.w;
    }
    if (blockIdx.x == 0) {
        if (tid < NCEFF) {
            int t = 0;
            #pragma unroll
            for (int p = 0; p < 8; p++) t += sCntPart[tid][p];
            sCnt[tid] = t;
        }
    }
    __syncthreads();
    if (blockIdx.x == 0 && tid == 0) {
        double cc = 0.0;
        #pragma unroll
        for (int k = 0; k < NCLASS; k++)
            cc += (double)sCnt[k] * (double)sCnt[k + NCLASS];
        sCntTerm = cc;
    }
    __syncthreads();

    // ---- per-dim fp64 contribution for this block's 16 dims ----------------
    double part = 0.0;
    if (tid < QPB * 4) {
        const int qq   = tid >> 2;
        const int comp = tid & 3;
        double s1 = 0.0, s2 = 0.0, dt = 0.0;
        #pragma unroll
        for (int k = 0; k < NCLASS; k++) {
            double av = (double)sTf[k][qq][comp];
            double bv = (double)sTf[k + NCLASS][qq][comp];
            s1 += av;
            s2 += bv;
            dt += av * bv;
        }
        part = s1 * s2 - 2.0 * dt;
    }
    // warp 0 reduce (lanes >=16 carry 0)
    #pragma unroll
    for (int o = 8; o > 0; o >>= 1)
        part += __shfl_xor_sync(0xFFFFFFFFu, part, o);
    if (tid == 0) {
        double blockpart = part + ((blockIdx.x == 0) ? sCntTerm : 0.0);
        atomicAdd(&g_sum, blockpart);    // 16 fp64 atomics total
    }

    // ---- 16-block election ----------------------------------------------------
    __threadfence();
    __syncthreads();
    if (tid == 0)
        sIsLast = (atomicAdd(&g_done, 1u) == (unsigned)(K3BLKS - 1));
    __syncthreads();
    if (!sIsLast) return;

    if (tid == 0) {
        double tot = atomicAdd(&g_sum, 0.0);   // coherent read of final sum
        out[0] = (float)(tot / ((double)n1 * (double)n2));
        g_sum  = 0.0;    // reset for next graph replay
        g_done = 0u;
    }
}

extern "C" void kernel_launch(void* const* d_in, const int* in_sizes, int n_in,
                              void* d_out, int out_size) {
    const float* mmd1 = (const float*)d_in[0];
    const float* mmd2 = (const float*)d_in[1];
    const int*   lab1 = (const int*)d_in[2];
    const int*   lab2 = (const int*)d_in[3];

    int n1 = in_sizes[0] / DIM;
    int n2 = in_sizes[1] / DIM;
    int ntot = n1 + n2;
    int nblk = (ntot + ROWS_PB - 1) / ROWS_PB;
    if (nblk > MAXBLK) nblk = MAXBLK;   // fixed shapes: 128 exactly

    ci_partial_kernel<<<nblk, NTHREADS>>>(mmd1, lab1, n1, mmd2, lab2, n2);
    ci_reduce_final_kernel<<<K3BLKS, NTHREADS>>>((float*)d_out, n1, n2);
}